// round 5
// baseline (speedup 1.0000x reference)
#include <cuda_runtime.h>

#define N 160
#define NP1 161
#define TWO_N 320
#define NCELLS (N * N)
#define BC 512
#define CH 8
#define BATCH 64
#define BIGV 1e10f
#define GAMMA 0.01f
#define INVG 100.0f

// Scratch: softmin gradient weights per cell (diag-major), 3 per cell.
__device__ float g_w[(size_t)BC * NCELLS * 3];
__device__ float g_sdtw[BC];
__device__ float g_lt[BC];

// Offset of anti-diagonal e (e = i + j, cells 1-based, e in [2, 2N]) in
// diag-major cell ordering.
__device__ __forceinline__ int diag_off(int e) {
    return (e <= N + 1) ? ((e - 2) * (e - 1)) / 2
                        : NCELLS - ((TWO_N + 1 - e) * (TWO_N + 2 - e)) / 2;
}

__global__ __launch_bounds__(160) void dtw_fwd_bwd_kernel(
    const float* __restrict__ input, const float* __restrict__ target) {
    const int prob = blockIdx.x;   // 0..511  (b*C + c)
    const int tid = threadIdx.x;   // 0..159

    __shared__ float sp[N];        // input row  (columns j of D)
    __shared__ float st[N];        // target row (rows i of D)
    __shared__ float Rb[3][NP1];   // rotating R diagonals, indexed by absolute j
    __shared__ float Eb[3][NP1 + 2];
    __shared__ int doff[TWO_N + 3];
    __shared__ float warp_sum[5];
    __shared__ float s_sdtw;

    sp[tid] = input[prob * N + tid];
    st[tid] = target[prob * N + tid];
    for (int e = tid + 2; e <= TWO_N + 2; e += 160)
        doff[e] = (e <= TWO_N) ? diag_off(e) : 0;

    if (tid == 0) {
        // diag 0 lives in buffer 0, diag 1 in buffer 1
        Rb[0][0] = 0.0f;   // R[0,0]
        Rb[1][0] = BIGV;   // R[1,0]
        Rb[1][1] = BIGV;   // R[0,1]
    }
    __syncthreads();

    float* gw = g_w + (size_t)prob * NCELLS * 3;

    // ---------------- forward: R + stash softmin weights ----------------
    for (int e = 2; e <= TWO_N; ++e) {
        const int cur = e % 3;
        const int b1 = (e + 2) % 3;  // diag e-1
        const int b2 = (e + 1) % 3;  // diag e-2
        const int j = tid + 1;
        const int jmin = max(1, e - N);
        const int jmax = min(N, e - 1);
        if (j >= jmin && j <= jmax) {
            const int i = e - j;
            float d = st[i - 1] - sp[j - 1];
            d *= d;
            const float a = Rb[b2][j - 1];  // diag parent R[i-1,j-1]
            const float b = Rb[b1][j];      // up   parent R[i-1,j]
            const float c = Rb[b1][j - 1];  // left parent R[i,j-1]
            const float mn = fminf(a, fminf(b, c));
            const float ea = __expf((mn - a) * INVG);
            const float eb = __expf((mn - b) * INVG);
            const float ec = __expf((mn - c) * INVG);
            const float s = ea + eb + ec;
            const float r = d + mn - GAMMA * __logf(s);
            Rb[cur][j] = r;
            const float inv = __fdividef(1.0f, s);
            float* wp = gw + (size_t)(doff[e] + (j - jmin)) * 3;
            wp[0] = ea * inv;  // w_diag
            wp[1] = eb * inv;  // w_up
            wp[2] = ec * inv;  // w_left
            if (e == TWO_N) s_sdtw = r;  // only j==N active here
        }
        if (tid == 0) {
            Rb[cur][0] = BIGV;              // R[e,0]
            if (e <= N) Rb[cur][e] = BIGV;  // R[0,e]
        }
        __syncthreads();
    }

    // ---------------- backward: E recursion, accumulate temporal ----------------
    float acc = 0.0f;
    for (int e = TWO_N; e >= 2; --e) {
        const int cur = e % 3;
        const int p1 = (e + 1) % 3;  // diag e+1
        const int p2 = (e + 2) % 3;  // diag e+2
        const int j = tid + 1;
        const int jmin = max(1, e - N);
        const int jmax = min(N, e - 1);
        if (j >= jmin && j <= jmax) {
            const int i = e - j;
            float Eij;
            if (e == TWO_N) {
                Eij = 1.0f;
            } else {
                Eij = 0.0f;
                const int jmin1 = max(1, e + 1 - N);
                if (i + 1 <= N) {  // child (i+1, j): we are its up-parent
                    const float* wp =
                        gw + (size_t)(doff[e + 1] + (j - jmin1)) * 3;
                    Eij += Eb[p1][j] * wp[1];
                }
                if (j + 1 <= N) {  // child (i, j+1): we are its left-parent
                    const float* wp =
                        gw + (size_t)(doff[e + 1] + (j + 1 - jmin1)) * 3;
                    Eij += Eb[p1][j + 1] * wp[2];
                }
                if (i + 1 <= N && j + 1 <= N) {  // child (i+1, j+1): diag parent
                    const int jmin2 = max(1, e + 2 - N);
                    const float* wp =
                        gw + (size_t)(doff[e + 2] + (j + 1 - jmin2)) * 3;
                    Eij += Eb[p2][j + 1] * wp[0];
                }
            }
            Eb[cur][j] = Eij;
            const float dd = (float)(i - j);
            acc += Eij * dd * dd;
        }
        __syncthreads();
    }

    // block reduction of temporal accumulator
    for (int o = 16; o; o >>= 1)
        acc += __shfl_down_sync(0xffffffffu, acc, o);
    if ((tid & 31) == 0) warp_sum[tid >> 5] = acc;
    __syncthreads();
    if (tid == 0) {
        float tot = 0.0f;
#pragma unroll
        for (int w = 0; w < 5; ++w) tot += warp_sum[w];
        g_lt[prob] = tot * (1.0f / (float)NCELLS);
        g_sdtw[prob] = s_sdtw;
    }
}

__global__ __launch_bounds__(BATCH) void dtw_reduce_kernel(
    float* __restrict__ out) {
    __shared__ float sh[BATCH];
    const int b = threadIdx.x;
    float ls = 0.0f, lt = 0.0f;
#pragma unroll
    for (int c = 0; c < CH; ++c) {
        ls += g_sdtw[b * CH + c];
        lt += g_lt[b * CH + c];
    }
    ls *= (1.0f / (float)CH);
    lt *= (1.0f / (float)CH);
    out[1 + b] = ls;              // loss_shape
    out[1 + BATCH + b] = lt;      // loss_temporal
    sh[b] = 0.5f * ls + 0.5f * lt;
    __syncthreads();
    if (b == 0) {
        float tot = 0.0f;
#pragma unroll
        for (int k = 0; k < BATCH; ++k) tot += sh[k];
        out[0] = tot * (1.0f / (float)BATCH);  // loss
    }
}

extern "C" void kernel_launch(void* const* d_in, const int* in_sizes, int n_in,
                              void* d_out, int out_size) {
    const float* input = (const float*)d_in[0];
    const float* target = (const float*)d_in[1];
    float* out = (float*)d_out;
    dtw_fwd_bwd_kernel<<<BC, 160>>>(input, target);
    dtw_reduce_kernel<<<1, BATCH>>>(out);
}

// round 6
// speedup vs baseline: 1.0073x; 1.0073x over previous
#include <cuda_runtime.h>

#define N 160
#define NP1 161
#define TWO_N 320
#define NCELLS (N * N)
#define BC 512
#define CH 8
#define BATCH 64
#define BIGV 1e10f
#define GAMMA 0.01f
#define INVG 100.0f

// Scratch: softmin gradient weights per cell (diag-major), 3 per cell.
__device__ float g_w[(size_t)BC * NCELLS * 3];
__device__ float g_sdtw[BC];
__device__ float g_lt[BC];

// Offset of anti-diagonal e (e = i + j, cells 1-based, e in [2, 2N]) in
// diag-major cell ordering.
__device__ __forceinline__ int diag_off(int e) {
    return (e <= N + 1) ? ((e - 2) * (e - 1)) / 2
                        : NCELLS - ((TWO_N + 1 - e) * (TWO_N + 2 - e)) / 2;
}

__global__ __launch_bounds__(160) void dtw_fwd_bwd_kernel(
    const float* __restrict__ input, const float* __restrict__ target) {
    const int prob = blockIdx.x;   // 0..511  (b*C + c)
    const int tid = threadIdx.x;   // 0..159

    __shared__ float sp[N];        // input row  (columns j of D)
    __shared__ float st[N];        // target row (rows i of D)
    __shared__ float Rb[3][NP1];   // rotating R diagonals, indexed by absolute j
    __shared__ float Eb[3][NP1 + 2];
    __shared__ int doff[TWO_N + 3];
    __shared__ float warp_sum[5];
    __shared__ float s_sdtw;

    sp[tid] = input[prob * N + tid];
    st[tid] = target[prob * N + tid];
    for (int e = tid + 2; e <= TWO_N + 2; e += 160)
        doff[e] = (e <= TWO_N) ? diag_off(e) : 0;

    if (tid == 0) {
        // diag 0 lives in buffer 0, diag 1 in buffer 1
        Rb[0][0] = 0.0f;   // R[0,0]
        Rb[1][0] = BIGV;   // R[1,0]
        Rb[1][1] = BIGV;   // R[0,1]
    }
    __syncthreads();

    float* gw = g_w + (size_t)prob * NCELLS * 3;

    // ---------------- forward: R + stash softmin weights ----------------
    for (int e = 2; e <= TWO_N; ++e) {
        const int cur = e % 3;
        const int b1 = (e + 2) % 3;  // diag e-1
        const int b2 = (e + 1) % 3;  // diag e-2
        const int j = tid + 1;
        const int jmin = max(1, e - N);
        const int jmax = min(N, e - 1);
        if (j >= jmin && j <= jmax) {
            const int i = e - j;
            float d = st[i - 1] - sp[j - 1];
            d *= d;
            const float a = Rb[b2][j - 1];  // diag parent R[i-1,j-1]
            const float b = Rb[b1][j];      // up   parent R[i-1,j]
            const float c = Rb[b1][j - 1];  // left parent R[i,j-1]
            const float mn = fminf(a, fminf(b, c));
            const float ea = __expf((mn - a) * INVG);
            const float eb = __expf((mn - b) * INVG);
            const float ec = __expf((mn - c) * INVG);
            const float s = ea + eb + ec;
            const float r = d + mn - GAMMA * __logf(s);
            Rb[cur][j] = r;
            const float inv = __fdividef(1.0f, s);
            float* wp = gw + (size_t)(doff[e] + (j - jmin)) * 3;
            wp[0] = ea * inv;  // w_diag
            wp[1] = eb * inv;  // w_up
            wp[2] = ec * inv;  // w_left
            if (e == TWO_N) s_sdtw = r;  // only j==N active here
        }
        if (tid == 0) {
            Rb[cur][0] = BIGV;              // R[e,0]
            if (e <= N) Rb[cur][e] = BIGV;  // R[0,e]
        }
        __syncthreads();
    }

    // ---------------- backward: E recursion, accumulate temporal ----------------
    float acc = 0.0f;
    for (int e = TWO_N; e >= 2; --e) {
        const int cur = e % 3;
        const int p1 = (e + 1) % 3;  // diag e+1
        const int p2 = (e + 2) % 3;  // diag e+2
        const int j = tid + 1;
        const int jmin = max(1, e - N);
        const int jmax = min(N, e - 1);
        if (j >= jmin && j <= jmax) {
            const int i = e - j;
            float Eij;
            if (e == TWO_N) {
                Eij = 1.0f;
            } else {
                Eij = 0.0f;
                const int jmin1 = max(1, e + 1 - N);
                if (i + 1 <= N) {  // child (i+1, j): we are its up-parent
                    const float* wp =
                        gw + (size_t)(doff[e + 1] + (j - jmin1)) * 3;
                    Eij += Eb[p1][j] * wp[1];
                }
                if (j + 1 <= N) {  // child (i, j+1): we are its left-parent
                    const float* wp =
                        gw + (size_t)(doff[e + 1] + (j + 1 - jmin1)) * 3;
                    Eij += Eb[p1][j + 1] * wp[2];
                }
                if (i + 1 <= N && j + 1 <= N) {  // child (i+1, j+1): diag parent
                    const int jmin2 = max(1, e + 2 - N);
                    const float* wp =
                        gw + (size_t)(doff[e + 2] + (j + 1 - jmin2)) * 3;
                    Eij += Eb[p2][j + 1] * wp[0];
                }
            }
            Eb[cur][j] = Eij;
            const float dd = (float)(i - j);
            acc += Eij * dd * dd;
        }
        __syncthreads();
    }

    // block reduction of temporal accumulator
    for (int o = 16; o; o >>= 1)
        acc += __shfl_down_sync(0xffffffffu, acc, o);
    if ((tid & 31) == 0) warp_sum[tid >> 5] = acc;
    __syncthreads();
    if (tid == 0) {
        float tot = 0.0f;
#pragma unroll
        for (int w = 0; w < 5; ++w) tot += warp_sum[w];
        g_lt[prob] = tot * (1.0f / (float)NCELLS);
        g_sdtw[prob] = s_sdtw;
    }
}

__global__ __launch_bounds__(BATCH) void dtw_reduce_kernel(
    float* __restrict__ out) {
    __shared__ float sh[BATCH];
    const int b = threadIdx.x;
    float ls = 0.0f, lt = 0.0f;
#pragma unroll
    for (int c = 0; c < CH; ++c) {
        ls += g_sdtw[b * CH + c];
        lt += g_lt[b * CH + c];
    }
    ls *= (1.0f / (float)CH);
    lt *= (1.0f / (float)CH);
    out[1 + b] = ls;              // loss_shape
    out[1 + BATCH + b] = lt;      // loss_temporal
    sh[b] = 0.5f * ls + 0.5f * lt;
    __syncthreads();
    if (b == 0) {
        float tot = 0.0f;
#pragma unroll
        for (int k = 0; k < BATCH; ++k) tot += sh[k];
        out[0] = tot * (1.0f / (float)BATCH);  // loss
    }
}

extern "C" void kernel_launch(void* const* d_in, const int* in_sizes, int n_in,
                              void* d_out, int out_size) {
    const float* input = (const float*)d_in[0];
    const float* target = (const float*)d_in[1];
    float* out = (float*)d_out;
    dtw_fwd_bwd_kernel<<<BC, 160>>>(input, target);
    dtw_reduce_kernel<<<1, BATCH>>>(out);
}

// round 7
// speedup vs baseline: 1.0125x; 1.0052x over previous
#include <cuda_runtime.h>

#define N 160
#define NP1 161
#define TWO_N 320
#define NCELLS (N * N)
#define BC 512
#define CH 8
#define BATCH 64
#define BIGV 1e10f
#define GAMMA 0.01f
#define INVG 100.0f

// Scratch: softmin gradient weights per cell (diag-major), 3 per cell.
__device__ float g_w[(size_t)BC * NCELLS * 3];
__device__ float g_sdtw[BC];
__device__ float g_lt[BC];

// Offset of anti-diagonal e (e = i + j, cells 1-based, e in [2, 2N]) in
// diag-major cell ordering.
__device__ __forceinline__ int diag_off(int e) {
    return (e <= N + 1) ? ((e - 2) * (e - 1)) / 2
                        : NCELLS - ((TWO_N + 1 - e) * (TWO_N + 2 - e)) / 2;
}

__global__ __launch_bounds__(160) void dtw_fwd_bwd_kernel(
    const float* __restrict__ input, const float* __restrict__ target) {
    const int prob = blockIdx.x;   // 0..511  (b*C + c)
    const int tid = threadIdx.x;   // 0..159

    __shared__ float sp[N];        // input row  (columns j of D)
    __shared__ float st[N];        // target row (rows i of D)
    __shared__ float Rb[3][NP1];   // rotating R diagonals, indexed by absolute j
    __shared__ float Eb[3][NP1 + 2];
    __shared__ int doff[TWO_N + 3];
    __shared__ float warp_sum[5];
    __shared__ float s_sdtw;

    sp[tid] = input[prob * N + tid];
    st[tid] = target[prob * N + tid];
    for (int e = tid + 2; e <= TWO_N + 2; e += 160)
        doff[e] = (e <= TWO_N) ? diag_off(e) : 0;

    if (tid == 0) {
        // diag 0 lives in buffer 0, diag 1 in buffer 1
        Rb[0][0] = 0.0f;   // R[0,0]
        Rb[1][0] = BIGV;   // R[1,0]
        Rb[1][1] = BIGV;   // R[0,1]
    }
    __syncthreads();

    float* gw = g_w + (size_t)prob * NCELLS * 3;

    // ---------------- forward: R + stash softmin weights ----------------
    for (int e = 2; e <= TWO_N; ++e) {
        const int cur = e % 3;
        const int b1 = (e + 2) % 3;  // diag e-1
        const int b2 = (e + 1) % 3;  // diag e-2
        const int j = tid + 1;
        const int jmin = max(1, e - N);
        const int jmax = min(N, e - 1);
        if (j >= jmin && j <= jmax) {
            const int i = e - j;
            float d = st[i - 1] - sp[j - 1];
            d *= d;
            const float a = Rb[b2][j - 1];  // diag parent R[i-1,j-1]
            const float b = Rb[b1][j];      // up   parent R[i-1,j]
            const float c = Rb[b1][j - 1];  // left parent R[i,j-1]
            const float mn = fminf(a, fminf(b, c));
            const float ea = __expf((mn - a) * INVG);
            const float eb = __expf((mn - b) * INVG);
            const float ec = __expf((mn - c) * INVG);
            const float s = ea + eb + ec;
            const float r = d + mn - GAMMA * __logf(s);
            Rb[cur][j] = r;
            const float inv = __fdividef(1.0f, s);
            float* wp = gw + (size_t)(doff[e] + (j - jmin)) * 3;
            wp[0] = ea * inv;  // w_diag
            wp[1] = eb * inv;  // w_up
            wp[2] = ec * inv;  // w_left
            if (e == TWO_N) s_sdtw = r;  // only j==N active here
        }
        if (tid == 0) {
            Rb[cur][0] = BIGV;              // R[e,0]
            if (e <= N) Rb[cur][e] = BIGV;  // R[0,e]
        }
        __syncthreads();
    }

    // ---------------- backward: E recursion, accumulate temporal ----------------
    float acc = 0.0f;
    for (int e = TWO_N; e >= 2; --e) {
        const int cur = e % 3;
        const int p1 = (e + 1) % 3;  // diag e+1
        const int p2 = (e + 2) % 3;  // diag e+2
        const int j = tid + 1;
        const int jmin = max(1, e - N);
        const int jmax = min(N, e - 1);
        if (j >= jmin && j <= jmax) {
            const int i = e - j;
            float Eij;
            if (e == TWO_N) {
                Eij = 1.0f;
            } else {
                Eij = 0.0f;
                const int jmin1 = max(1, e + 1 - N);
                if (i + 1 <= N) {  // child (i+1, j): we are its up-parent
                    const float* wp =
                        gw + (size_t)(doff[e + 1] + (j - jmin1)) * 3;
                    Eij += Eb[p1][j] * wp[1];
                }
                if (j + 1 <= N) {  // child (i, j+1): we are its left-parent
                    const float* wp =
                        gw + (size_t)(doff[e + 1] + (j + 1 - jmin1)) * 3;
                    Eij += Eb[p1][j + 1] * wp[2];
                }
                if (i + 1 <= N && j + 1 <= N) {  // child (i+1, j+1): diag parent
                    const int jmin2 = max(1, e + 2 - N);
                    const float* wp =
                        gw + (size_t)(doff[e + 2] + (j + 1 - jmin2)) * 3;
                    Eij += Eb[p2][j + 1] * wp[0];
                }
            }
            Eb[cur][j] = Eij;
            const float dd = (float)(i - j);
            acc += Eij * dd * dd;
        }
        __syncthreads();
    }

    // block reduction of temporal accumulator
    for (int o = 16; o; o >>= 1)
        acc += __shfl_down_sync(0xffffffffu, acc, o);
    if ((tid & 31) == 0) warp_sum[tid >> 5] = acc;
    __syncthreads();
    if (tid == 0) {
        float tot = 0.0f;
#pragma unroll
        for (int w = 0; w < 5; ++w) tot += warp_sum[w];
        g_lt[prob] = tot * (1.0f / (float)NCELLS);
        g_sdtw[prob] = s_sdtw;
    }
}

__global__ __launch_bounds__(BATCH) void dtw_reduce_kernel(
    float* __restrict__ out) {
    __shared__ float sh[BATCH];
    const int b = threadIdx.x;
    float ls = 0.0f, lt = 0.0f;
#pragma unroll
    for (int c = 0; c < CH; ++c) {
        ls += g_sdtw[b * CH + c];
        lt += g_lt[b * CH + c];
    }
    ls *= (1.0f / (float)CH);
    lt *= (1.0f / (float)CH);
    out[1 + b] = ls;              // loss_shape
    out[1 + BATCH + b] = lt;      // loss_temporal
    sh[b] = 0.5f * ls + 0.5f * lt;
    __syncthreads();
    if (b == 0) {
        float tot = 0.0f;
#pragma unroll
        for (int k = 0; k < BATCH; ++k) tot += sh[k];
        out[0] = tot * (1.0f / (float)BATCH);  // loss
    }
}

extern "C" void kernel_launch(void* const* d_in, const int* in_sizes, int n_in,
                              void* d_out, int out_size) {
    const float* input = (const float*)d_in[0];
    const float* target = (const float*)d_in[1];
    float* out = (float*)d_out;
    dtw_fwd_bwd_kernel<<<BC, 160>>>(input, target);
    dtw_reduce_kernel<<<1, BATCH>>>(out);
}